// round 4
// baseline (speedup 1.0000x reference)
#include <cuda_runtime.h>
#include <cuda_bf16.h>
#include <cstdint>

#define N_NODES 100000
#define N_EDGES 1000000
#define N_GRAPH 256
#define SCAN_CH 840
#define SCAN_BLOCKS 120   // 120*840 = 100800 >= 100000

// ---------------- scratch (static device globals; no allocation) ----------------
__device__ float g_h1[N_NODES * 64];          // layer-1 GEMM output (pre-agg)
__device__ float g_h2[N_NODES * 64];          // fused agg1+gemm2 output (pre-agg for layer 2)
__device__ int   g_deg[N_NODES];
__device__ float g_dinv[N_NODES];
__device__ int   g_rowptr[N_NODES + 1];
__device__ int   g_pos[N_NODES];
__device__ int   g_csr[N_EDGES];
__device__ int   g_bsum[SCAN_BLOCKS];
__device__ int   g_boff[SCAN_BLOCKS];
__device__ int   g_cnt[N_GRAPH];
__device__ float g_gsum[N_GRAPH * 64];

// ---------------- zero all accumulators in one launch ----------------
__global__ void zero_kernel()
{
    int i = blockIdx.x * blockDim.x + threadIdx.x;
    if (i < N_NODES) g_deg[i] = 0;
    if (i < N_GRAPH) g_cnt[i] = 0;
    if (i < N_GRAPH * 64) g_gsum[i] = 0.f;
}

// ---------------- degree + batch histograms (merged) ----------------
__global__ void hist_kernel(const int* __restrict__ ei, const int* __restrict__ batch)
{
    int e = blockIdx.x * blockDim.x + threadIdx.x;
    if (e < N_EDGES) {
        int d = ei[N_EDGES + e];   // dst
        if ((unsigned)d < (unsigned)N_NODES) atomicAdd(&g_deg[d], 1);
    }
    if (e < N_NODES) {
        int g = batch[e];
        if ((unsigned)g < (unsigned)N_GRAPH) atomicAdd(&g_cnt[g], 1);
    }
}

// ---------------- 3-kernel exclusive prefix scan over deg -> rowptr ----------------
__global__ void scan_part_kernel()
{
    int b = blockIdx.x;
    int start = b * SCAN_CH;
    int end   = min(start + SCAN_CH, N_NODES);
    __shared__ int wsum[8];
    __shared__ int tile_total;
    int lane = threadIdx.x & 31, wid = threadIdx.x >> 5;
    int carry = 0;
    for (int base = start; base < end; base += 256) {
        int i = base + (int)threadIdx.x;
        int v = (i < end) ? g_deg[i] : 0;
        int incl = v;
#pragma unroll
        for (int o = 1; o < 32; o <<= 1) {
            int t = __shfl_up_sync(0xffffffffu, incl, o);
            if (lane >= o) incl += t;
        }
        if (lane == 31) wsum[wid] = incl;
        __syncthreads();
        if (threadIdx.x == 0) {
            int run = 0;
#pragma unroll
            for (int w = 0; w < 8; w++) { int t = wsum[w]; wsum[w] = run; run += t; }
            tile_total = run;
        }
        __syncthreads();
        if (i < end) g_rowptr[i] = incl - v + wsum[wid] + carry;
        carry += tile_total;
        __syncthreads();
    }
    if (threadIdx.x == 0) g_bsum[b] = carry;
}

// single-warp parallel scan over SCAN_BLOCKS partials
__global__ void scan_mid_kernel()
{
    int lane = threadIdx.x;    // 32 threads
    int carry = 0;
#pragma unroll
    for (int c = 0; c < (SCAN_BLOCKS + 31) / 32; c++) {
        int i = c * 32 + lane;
        int v = (i < SCAN_BLOCKS) ? g_bsum[i] : 0;
        int incl = v;
#pragma unroll
        for (int o = 1; o < 32; o <<= 1) {
            int t = __shfl_up_sync(0xffffffffu, incl, o);
            if (lane >= o) incl += t;
        }
        if (i < SCAN_BLOCKS) g_boff[i] = carry + incl - v;
        carry += __shfl_sync(0xffffffffu, incl, 31);
    }
}

__global__ void scan_add_kernel()
{
    int i = blockIdx.x * blockDim.x + threadIdx.x;
    if (i < N_NODES) {
        int r = g_rowptr[i] + g_boff[i / SCAN_CH];
        g_rowptr[i] = r;
        g_pos[i] = r;
        g_dinv[i] = rsqrtf((float)g_deg[i] + 1.0f);
    }
    if (i == 0) g_rowptr[N_NODES] = N_EDGES;
}

// ---------------- CSR fill ----------------
__global__ void fill_kernel(const int* __restrict__ ei)
{
    int e = blockIdx.x * blockDim.x + threadIdx.x;
    if (e < N_EDGES) {
        int s = ei[e];
        int d = ei[N_EDGES + e];
        if ((unsigned)s < (unsigned)N_NODES && (unsigned)d < (unsigned)N_NODES) {
            int p = atomicAdd(&g_pos[d], 1);
            if ((unsigned)p < (unsigned)N_EDGES) g_csr[p] = s;
        }
    }
}

// ---------------- 64x64 GEMM: Y[n,64] = X[n,64] @ W[64,64] ----------------
__global__ __launch_bounds__(128) void gemm64_kernel(const float* __restrict__ X,
                                                     const float* __restrict__ W,
                                                     float* __restrict__ Y)
{
    __shared__ float Ws[64 * 64];
    for (int i = threadIdx.x; i < 64 * 64; i += blockDim.x) Ws[i] = W[i];
    __syncthreads();
    int row = blockIdx.x * blockDim.x + threadIdx.x;
    if (row >= N_NODES) return;

    float acc[64];
#pragma unroll
    for (int j = 0; j < 64; j++) acc[j] = 0.f;

    const float4* xr = reinterpret_cast<const float4*>(X + (size_t)row * 64);
#pragma unroll 2
    for (int k4 = 0; k4 < 16; k4++) {
        float4 xv = __ldg(xr + k4);
        const float* wr = &Ws[(k4 * 4) * 64];
#pragma unroll
        for (int j = 0; j < 64; j++) {
            float a = acc[j];
            a = fmaf(xv.x, wr[j],        a);
            a = fmaf(xv.y, wr[64 + j],   a);
            a = fmaf(xv.z, wr[128 + j],  a);
            a = fmaf(xv.w, wr[192 + j],  a);
            acc[j] = a;
        }
    }
    float4* yr = reinterpret_cast<float4*>(Y + (size_t)row * 64);
#pragma unroll
    for (int j4 = 0; j4 < 16; j4++)
        yr[j4] = make_float4(acc[4 * j4], acc[4 * j4 + 1], acc[4 * j4 + 2], acc[4 * j4 + 3]);
}

// ---------------- aggregation core: warp computes relu(agg + bias) for one node ----------------
// v (float2 per lane) = relu( dinv[i]*sum_e dinv[src]*h[src] + dinv[i]^2*h[i] + bias )
__device__ __forceinline__ float2 agg_node(const float2* __restrict__ h,
                                           const float* __restrict__ bias,
                                           int node, int lane)
{
    float di = g_dinv[node];
    float2 self = __ldg(&h[(size_t)node * 32 + lane]);
    float d2 = di * di;
    float2 acc = make_float2(d2 * self.x, d2 * self.y);

    int e  = g_rowptr[node];
    int e1 = g_rowptr[node + 1];
    // unroll 4: front-batch independent loads for MLP
    for (; e + 3 < e1; e += 4) {
        int s0 = g_csr[e], s1 = g_csr[e + 1], s2 = g_csr[e + 2], s3 = g_csr[e + 3];
        float w0 = __ldg(&g_dinv[s0]);
        float w1 = __ldg(&g_dinv[s1]);
        float w2 = __ldg(&g_dinv[s2]);
        float w3 = __ldg(&g_dinv[s3]);
        float2 h0 = __ldg(&h[(size_t)s0 * 32 + lane]);
        float2 h1 = __ldg(&h[(size_t)s1 * 32 + lane]);
        float2 h2 = __ldg(&h[(size_t)s2 * 32 + lane]);
        float2 h3 = __ldg(&h[(size_t)s3 * 32 + lane]);
        w0 *= di; w1 *= di; w2 *= di; w3 *= di;
        acc.x = fmaf(w0, h0.x, acc.x); acc.y = fmaf(w0, h0.y, acc.y);
        acc.x = fmaf(w1, h1.x, acc.x); acc.y = fmaf(w1, h1.y, acc.y);
        acc.x = fmaf(w2, h2.x, acc.x); acc.y = fmaf(w2, h2.y, acc.y);
        acc.x = fmaf(w3, h3.x, acc.x); acc.y = fmaf(w3, h3.y, acc.y);
    }
    for (; e < e1; e++) {
        int s0 = g_csr[e];
        float w0 = di * __ldg(&g_dinv[s0]);
        float2 h0 = __ldg(&h[(size_t)s0 * 32 + lane]);
        acc.x = fmaf(w0, h0.x, acc.x); acc.y = fmaf(w0, h0.y, acc.y);
    }
    float2 v;
    v.x = fmaxf(acc.x + __ldg(&bias[lane * 2]), 0.f);
    v.y = fmaxf(acc.y + __ldg(&bias[lane * 2 + 1]), 0.f);
    return v;
}

// ---------------- fused: layer-1 aggregation + layer-2 GEMM ----------------
// g_h2[row] = relu(agg(h1)[row] + b1) @ W2
__global__ __launch_bounds__(256) void agg_gemm_kernel(const float* __restrict__ hraw,
                                                       const float* __restrict__ bias,
                                                       const float* __restrict__ W2)
{
    __shared__ float Ws[64 * 64];                 // W2, row-major
    __shared__ float vbuf[8][64];                 // per-warp aggregated row
    for (int i = threadIdx.x; i < 64 * 64; i += blockDim.x) Ws[i] = W2[i];
    __syncthreads();

    int gw = (blockIdx.x * blockDim.x + threadIdx.x) >> 5;
    if (gw >= N_NODES) return;
    int lane = threadIdx.x & 31;
    int w = (threadIdx.x >> 5) & 7;

    float2 v = agg_node(reinterpret_cast<const float2*>(hraw), bias, gw, lane);
    vbuf[w][lane * 2]     = v.x;
    vbuf[w][lane * 2 + 1] = v.y;
    __syncwarp();

    // row @ W2 : lane j computes output features 2j, 2j+1
    const float2* Ws2 = reinterpret_cast<const float2*>(Ws);
    float2 o = make_float2(0.f, 0.f);
#pragma unroll 8
    for (int k = 0; k < 64; k++) {
        float vk = vbuf[w][k];
        float2 wv = Ws2[k * 32 + lane];
        o.x = fmaf(vk, wv.x, o.x);
        o.y = fmaf(vk, wv.y, o.y);
    }
    reinterpret_cast<float2*>(g_h2)[(size_t)gw * 32 + lane] = o;
}

// ---------------- layer-2 aggregation + fused mean-pool accumulation ----------------
__global__ __launch_bounds__(256) void agg_pool_kernel(const float* __restrict__ hraw,
                                                       const float* __restrict__ bias,
                                                       const int* __restrict__ batch)
{
    int gw = (blockIdx.x * blockDim.x + threadIdx.x) >> 5;
    if (gw >= N_NODES) return;
    int lane = threadIdx.x & 31;

    float2 v = agg_node(reinterpret_cast<const float2*>(hraw), bias, gw, lane);

    int g = batch[gw];
    if ((unsigned)g < (unsigned)N_GRAPH) {
        atomicAdd(&g_gsum[g * 64 + lane * 2], v.x);
        atomicAdd(&g_gsum[g * 64 + lane * 2 + 1], v.y);
    }
}

// ---------------- threefry-2x32, key = (0, 42) ----------------
__device__ __forceinline__ void threefry2x32_42(unsigned c0, unsigned c1,
                                                unsigned& o0, unsigned& o1)
{
    const unsigned k0 = 0u, k1 = 42u, k2 = 0u ^ 42u ^ 0x1BD11BDAu;
    unsigned x0 = c0 + k0, x1 = c1 + k1;
#define TF_ROUND(r) { x0 += x1; x1 = (x1 << (r)) | (x1 >> (32 - (r))); x1 ^= x0; }
    TF_ROUND(13) TF_ROUND(15) TF_ROUND(26) TF_ROUND(6)
    x0 += k1; x1 += k2 + 1u;
    TF_ROUND(17) TF_ROUND(29) TF_ROUND(16) TF_ROUND(24)
    x0 += k2; x1 += k0 + 2u;
    TF_ROUND(13) TF_ROUND(15) TF_ROUND(26) TF_ROUND(6)
    x0 += k0; x1 += k1 + 3u;
    TF_ROUND(17) TF_ROUND(29) TF_ROUND(16) TF_ROUND(24)
    x0 += k1; x1 += k2 + 4u;
    TF_ROUND(13) TF_ROUND(15) TF_ROUND(26) TF_ROUND(6)
    x0 += k2; x1 += k0 + 5u;
#undef TF_ROUND
    o0 = x0; o1 = x1;
}

// ---------------- head: pool -> mu/logvar -> z -> decoder ----------------
__global__ __launch_bounds__(64) void head_kernel(
    const float* __restrict__ Wmu, const float* __restrict__ bmu,
    const float* __restrict__ Wlv, const float* __restrict__ blv,
    const float* __restrict__ Wd1, const float* __restrict__ bd1,
    const float* __restrict__ Wd2, const float* __restrict__ bd2,
    float* __restrict__ out)
{
    int g = blockIdx.x;
    int t = threadIdx.x;
    __shared__ float pooled[64];
    __shared__ float zs[32];
    __shared__ float hdec[64];

    float c = fmaxf((float)g_cnt[g], 1.0f);
    pooled[t] = g_gsum[g * 64 + t] / c;
    __syncthreads();

    if (t < 32) {
        float mu = __ldg(&bmu[t]), lv = __ldg(&blv[t]);
#pragma unroll 8
        for (int k = 0; k < 64; k++) {
            float p = pooled[k];
            mu = fmaf(p, __ldg(&Wmu[k * 32 + t]), mu);
            lv = fmaf(p, __ldg(&Wlv[k * 32 + t]), lv);
        }
        // jax.random.normal(key(42), (256,32)), threefry_partitionable:
        // bits[i] = xor(threefry2x32(key, (0, i)))
        unsigned idx = (unsigned)(g * 32 + t);
        unsigned b0, b1;
        threefry2x32_42(0u, idx, b0, b1);
        unsigned bits = b0 ^ b1;
        float f = __uint_as_float((bits >> 9) | 0x3f800000u) - 1.0f;   // [0,1)
        const float LO = -0.99999994f;                                  // nextafter(-1,0)
        float u = fmaxf(LO, f * (1.0f - LO) + LO);
        float eps = 1.41421356237309515f * erfinvf(u);
        float z = mu + eps * expf(0.5f * lv);
        zs[t] = z;
        out[16384 + g * 32 + t] = mu;
        out[24576 + g * 32 + t] = lv;
    }
    __syncthreads();

    float hv = __ldg(&bd1[t]);
#pragma unroll 8
    for (int k = 0; k < 32; k++) hv = fmaf(zs[k], __ldg(&Wd1[k * 64 + t]), hv);
    hdec[t] = fmaxf(hv, 0.f);
    __syncthreads();

    float rv = __ldg(&bd2[t]);
#pragma unroll 8
    for (int k = 0; k < 64; k++) rv = fmaf(hdec[k], __ldg(&Wd2[k * 64 + t]), rv);
    out[g * 64 + t] = rv;
}

// ---------------- launch ----------------
extern "C" void kernel_launch(void* const* d_in, const int* in_sizes, int n_in,
                              void* d_out, int out_size)
{
    const float* x     = (const float*)d_in[0];
    const int*   ei    = (const int*)d_in[1];     // int64 inputs delivered as int32
    const int*   batch = (const int*)d_in[2];
    const float* W1  = (const float*)d_in[3];  const float* b1  = (const float*)d_in[4];
    const float* W2  = (const float*)d_in[5];  const float* b2  = (const float*)d_in[6];
    const float* Wmu = (const float*)d_in[7];  const float* bmu = (const float*)d_in[8];
    const float* Wlv = (const float*)d_in[9];  const float* blv = (const float*)d_in[10];
    const float* Wd1 = (const float*)d_in[11]; const float* bd1 = (const float*)d_in[12];
    const float* Wd2 = (const float*)d_in[13]; const float* bd2 = (const float*)d_in[14];
    float* out = (float*)d_out;

    void *p_h1, *p_h2;
    cudaGetSymbolAddress(&p_h1, g_h1);
    cudaGetSymbolAddress(&p_h2, g_h2);
    float* h1 = (float*)p_h1;
    float* h2 = (float*)p_h2;

    // graph structure (shared by both conv layers)
    zero_kernel<<<(N_NODES + 255) / 256, 256>>>();
    hist_kernel<<<(N_EDGES + 255) / 256, 256>>>(ei, batch);
    scan_part_kernel<<<SCAN_BLOCKS, 256>>>();
    scan_mid_kernel<<<1, 32>>>();
    scan_add_kernel<<<(N_NODES + 255) / 256, 256>>>();
    fill_kernel<<<(N_EDGES + 255) / 256, 256>>>(ei);

    int agg_grid = (N_NODES * 32 + 255) / 256;

    // layer 1 GEMM
    gemm64_kernel<<<(N_NODES + 127) / 128, 128>>>(x, W1, h1);
    // fused: layer-1 aggregation + layer-2 GEMM  -> g_h2
    agg_gemm_kernel<<<agg_grid, 256>>>(h1, b1, W2);
    // layer-2 aggregation + mean-pool accumulation
    agg_pool_kernel<<<agg_grid, 256>>>(h2, b2, batch);
    // head
    head_kernel<<<N_GRAPH, 64>>>(Wmu, bmu, Wlv, blv, Wd1, bd1, Wd2, bd2, out);
}

// round 7
// speedup vs baseline: 1.2908x; 1.2908x over previous
#include <cuda_runtime.h>
#include <cuda_bf16.h>
#include <cstdint>

#define N_NODES 100000
#define N_EDGES 1000000
#define N_GRAPH 256
#define SCAN_CH 840
#define SCAN_BLOCKS 120   // 120*840 = 100800 >= 100000

// ---------------- scratch ----------------
__device__ float g_h1[N_NODES * 64];
__device__ float g_h2[N_NODES * 64];
__device__ int   g_deg[N_NODES];
__device__ float g_dinv[N_NODES];
__device__ int   g_rowptr[N_NODES + 1];
__device__ int   g_pos[N_NODES];
__device__ int   g_csr[N_EDGES];
__device__ int   g_cnt[N_GRAPH];
__device__ float g_gsum[N_GRAPH * 64];

// ---------------- packed f32x2 helpers ----------------
__device__ __forceinline__ unsigned long long pack2(float lo, float hi)
{
    unsigned long long r;
    asm("mov.b64 %0, {%1, %2};" : "=l"(r) : "f"(lo), "f"(hi));
    return r;
}
__device__ __forceinline__ void unpack2(unsigned long long v, float& lo, float& hi)
{
    asm("mov.b64 {%0, %1}, %2;" : "=f"(lo), "=f"(hi) : "l"(v));
}
__device__ __forceinline__ void ffma2(unsigned long long& d, unsigned long long a,
                                      unsigned long long b)
{
    asm("fma.rn.f32x2 %0, %1, %2, %0;" : "+l"(d) : "l"(a), "l"(b));
}

// ---------------- zero ----------------
__global__ void zero_kernel()
{
    int i = blockIdx.x * blockDim.x + threadIdx.x;
    if (i < N_NODES) g_deg[i] = 0;
    if (i < N_GRAPH) g_cnt[i] = 0;
    if (i < N_GRAPH * 64) g_gsum[i] = 0.f;
}

// ---------------- histograms ----------------
__global__ void hist_kernel(const int* __restrict__ ei, const int* __restrict__ batch)
{
    int e = blockIdx.x * blockDim.x + threadIdx.x;
    if (e < N_EDGES) {
        int d = ei[N_EDGES + e];
        if ((unsigned)d < (unsigned)N_NODES) atomicAdd(&g_deg[d], 1);
    }
    if (e < N_NODES) {
        int g = batch[e];
        if ((unsigned)g < (unsigned)N_GRAPH) atomicAdd(&g_cnt[g], 1);
    }
}

// ---------------- single-kernel scan: rowptr/pos/dinv ----------------
// Each block independently computes the global prefix of its chunk (redundant
// reads of deg[0..start) — ~24MB total L2, no inter-block sync), then scans
// its own chunk.
__global__ __launch_bounds__(256) void scan_all_kernel()
{
    int b = blockIdx.x;
    int start = b * SCAN_CH;
    int end   = min(start + SCAN_CH, N_NODES);
    int lane = threadIdx.x & 31, wid = threadIdx.x >> 5;

    // --- global prefix: sum deg[0..start) ---
    int psum = 0;
#pragma unroll 4
    for (int i = threadIdx.x; i < start; i += 256) psum += g_deg[i];
#pragma unroll
    for (int o = 16; o > 0; o >>= 1) psum += __shfl_down_sync(0xffffffffu, psum, o);
    __shared__ int wred[8];
    __shared__ int s_off;
    if (lane == 0) wred[wid] = psum;
    __syncthreads();
    if (threadIdx.x == 0) {
        int t = 0;
#pragma unroll
        for (int w = 0; w < 8; w++) t += wred[w];
        s_off = t;
    }
    __syncthreads();
    int carry = s_off;

    // --- chunk scan ---
    __shared__ int wsum[8];
    __shared__ int tile_total;
    for (int base = start; base < end; base += 256) {
        int i = base + (int)threadIdx.x;
        int dv = (i < end) ? g_deg[i] : 0;
        int incl = dv;
#pragma unroll
        for (int o = 1; o < 32; o <<= 1) {
            int t = __shfl_up_sync(0xffffffffu, incl, o);
            if (lane >= o) incl += t;
        }
        if (lane == 31) wsum[wid] = incl;
        __syncthreads();
        if (threadIdx.x == 0) {
            int run = 0;
#pragma unroll
            for (int w = 0; w < 8; w++) { int t = wsum[w]; wsum[w] = run; run += t; }
            tile_total = run;
        }
        __syncthreads();
        if (i < end) {
            int r = incl - dv + wsum[wid] + carry;
            g_rowptr[i] = r;
            g_pos[i] = r;
            g_dinv[i] = rsqrtf((float)dv + 1.0f);
        }
        carry += tile_total;
        __syncthreads();
    }
    if (b == SCAN_BLOCKS - 1 && threadIdx.x == 0) g_rowptr[N_NODES] = N_EDGES;
}

// ---------------- CSR fill ----------------
__global__ void fill_kernel(const int* __restrict__ ei)
{
    int e = blockIdx.x * blockDim.x + threadIdx.x;
    if (e < N_EDGES) {
        int s = ei[e];
        int d = ei[N_EDGES + e];
        if ((unsigned)s < (unsigned)N_NODES && (unsigned)d < (unsigned)N_NODES) {
            int p = atomicAdd(&g_pos[d], 1);
            if ((unsigned)p < (unsigned)N_EDGES) g_csr[p] = s;
        }
    }
}

// ---------------- pure aggregation: S = A_hat @ X  (warp per node) ----------------
__global__ __launch_bounds__(256) void agg_kernel(const float* __restrict__ hraw,
                                                  float* __restrict__ hout)
{
    int gw = (blockIdx.x * blockDim.x + threadIdx.x) >> 5;
    if (gw >= N_NODES) return;
    int lane = threadIdx.x & 31;

    const float2* h = reinterpret_cast<const float2*>(hraw);
    float di = g_dinv[gw];
    float2 self = __ldg(&h[(size_t)gw * 32 + lane]);
    float d2 = di * di;
    float2 acc = make_float2(d2 * self.x, d2 * self.y);

    int e  = g_rowptr[gw];
    int e1 = g_rowptr[gw + 1];
    for (; e + 3 < e1; e += 4) {
        int s0 = g_csr[e], s1 = g_csr[e + 1], s2 = g_csr[e + 2], s3 = g_csr[e + 3];
        float w0 = __ldg(&g_dinv[s0]);
        float w1 = __ldg(&g_dinv[s1]);
        float w2 = __ldg(&g_dinv[s2]);
        float w3 = __ldg(&g_dinv[s3]);
        float2 h0 = __ldg(&h[(size_t)s0 * 32 + lane]);
        float2 h1 = __ldg(&h[(size_t)s1 * 32 + lane]);
        float2 h2 = __ldg(&h[(size_t)s2 * 32 + lane]);
        float2 h3 = __ldg(&h[(size_t)s3 * 32 + lane]);
        w0 *= di; w1 *= di; w2 *= di; w3 *= di;
        acc.x = fmaf(w0, h0.x, acc.x); acc.y = fmaf(w0, h0.y, acc.y);
        acc.x = fmaf(w1, h1.x, acc.x); acc.y = fmaf(w1, h1.y, acc.y);
        acc.x = fmaf(w2, h2.x, acc.x); acc.y = fmaf(w2, h2.y, acc.y);
        acc.x = fmaf(w3, h3.x, acc.x); acc.y = fmaf(w3, h3.y, acc.y);
    }
    for (; e < e1; e++) {
        int s0 = g_csr[e];
        float w0 = di * __ldg(&g_dinv[s0]);
        float2 h0 = __ldg(&h[(size_t)s0 * 32 + lane]);
        acc.x = fmaf(w0, h0.x, acc.x); acc.y = fmaf(w0, h0.y, acc.y);
    }
    reinterpret_cast<float2*>(hout)[(size_t)gw * 32 + lane] = acc;
}

// ---------------- blocked GEMM: Y = relu(X @ W + b), optional fused pool ----------------
// Tile: 128 M x 64 N, 256 threads, thread tile 8M x 4N.
// f32x2 lanes carry (even-k, odd-k) partial sums; cross-lane add at the end.
template <int POOL>
__global__ __launch_bounds__(256) void gemm_kernel(const float* __restrict__ X,
                                                   const float* __restrict__ W,
                                                   const float* __restrict__ bias,
                                                   float* __restrict__ Y,
                                                   const int* __restrict__ batch)
{
    __shared__ float Xs[128][68];     // padded
    __shared__ float Ws[64][64];
    int tid = threadIdx.x;
    int mbase = blockIdx.x * 128;

    // stage X (128x64) — 8 float4 per thread
#pragma unroll
    for (int t = 0; t < 8; t++) {
        int i = tid + t * 256;
        int r = i >> 4, c4 = (i & 15) * 4;
        int grow = mbase + r;
        float4 v = make_float4(0.f, 0.f, 0.f, 0.f);
        if (grow < N_NODES) v = __ldg((const float4*)(X + (size_t)grow * 64 + c4));
        *(float4*)&Xs[r][c4] = v;
    }
    // stage W (64x64) — 4 float4 per thread
#pragma unroll
    for (int t = 0; t < 4; t++) {
        int i = tid + t * 256;
        int k = i >> 4, c4 = (i & 15) * 4;
        *(float4*)&Ws[k][c4] = __ldg((const float4*)(W + k * 64 + c4));
    }
    __syncthreads();

    int tg_m = tid >> 4;          // 0..15
    int tg_n = tid & 15;          // 0..15
    int mloc = tg_m * 8;
    int n0 = tg_n * 4;

    unsigned long long acc[8][4];
#pragma unroll
    for (int r = 0; r < 8; r++)
#pragma unroll
        for (int c = 0; c < 4; c++) acc[r][c] = 0ull;

#pragma unroll 4
    for (int k = 0; k < 64; k += 2) {
        float4 wa = *(const float4*)&Ws[k][n0];
        float4 wb = *(const float4*)&Ws[k + 1][n0];
        unsigned long long wp0 = pack2(wa.x, wb.x);
        unsigned long long wp1 = pack2(wa.y, wb.y);
        unsigned long long wp2 = pack2(wa.z, wb.z);
        unsigned long long wp3 = pack2(wa.w, wb.w);
#pragma unroll
        for (int r = 0; r < 8; r++) {
            unsigned long long xp = *(const unsigned long long*)&Xs[mloc + r][k];
            ffma2(acc[r][0], xp, wp0);
            ffma2(acc[r][1], xp, wp1);
            ffma2(acc[r][2], xp, wp2);
            ffma2(acc[r][3], xp, wp3);
        }
    }

    float4 bv = __ldg((const float4*)(bias + n0));

    if (POOL) {
        // batch is sorted: segment-accumulate this thread's 8 consecutive rows
        float p0 = 0.f, p1 = 0.f, p2 = 0.f, p3 = 0.f;
        int curg = -1;
#pragma unroll
        for (int r = 0; r < 8; r++) {
            int grow = mbase + mloc + r;
            if (grow >= N_NODES) break;
            int g = batch[grow];
            if (g != curg) {
                if (curg >= 0 && (unsigned)curg < (unsigned)N_GRAPH) {
                    atomicAdd(&g_gsum[curg * 64 + n0],     p0);
                    atomicAdd(&g_gsum[curg * 64 + n0 + 1], p1);
                    atomicAdd(&g_gsum[curg * 64 + n0 + 2], p2);
                    atomicAdd(&g_gsum[curg * 64 + n0 + 3], p3);
                }
                curg = g; p0 = p1 = p2 = p3 = 0.f;
            }
            float lo, hi;
            unpack2(acc[r][0], lo, hi); p0 += fmaxf(lo + hi + bv.x, 0.f);
            unpack2(acc[r][1], lo, hi); p1 += fmaxf(lo + hi + bv.y, 0.f);
            unpack2(acc[r][2], lo, hi); p2 += fmaxf(lo + hi + bv.z, 0.f);
            unpack2(acc[r][3], lo, hi); p3 += fmaxf(lo + hi + bv.w, 0.f);
        }
        if (curg >= 0 && (unsigned)curg < (unsigned)N_GRAPH) {
            atomicAdd(&g_gsum[curg * 64 + n0],     p0);
            atomicAdd(&g_gsum[curg * 64 + n0 + 1], p1);
            atomicAdd(&g_gsum[curg * 64 + n0 + 2], p2);
            atomicAdd(&g_gsum[curg * 64 + n0 + 3], p3);
        }
    } else {
#pragma unroll
        for (int r = 0; r < 8; r++) {
            int grow = mbase + mloc + r;
            if (grow >= N_NODES) break;
            float lo, hi;
            float4 o;
            unpack2(acc[r][0], lo, hi); o.x = fmaxf(lo + hi + bv.x, 0.f);
            unpack2(acc[r][1], lo, hi); o.y = fmaxf(lo + hi + bv.y, 0.f);
            unpack2(acc[r][2], lo, hi); o.z = fmaxf(lo + hi + bv.z, 0.f);
            unpack2(acc[r][3], lo, hi); o.w = fmaxf(lo + hi + bv.w, 0.f);
            *(float4*)(Y + (size_t)grow * 64 + n0) = o;
        }
    }
}

// ---------------- threefry-2x32, key = (0, 42) ----------------
__device__ __forceinline__ void threefry2x32_42(unsigned c0, unsigned c1,
                                                unsigned& o0, unsigned& o1)
{
    const unsigned k0 = 0u, k1 = 42u, k2 = 0u ^ 42u ^ 0x1BD11BDAu;
    unsigned x0 = c0 + k0, x1 = c1 + k1;
#define TF_ROUND(r) { x0 += x1; x1 = (x1 << (r)) | (x1 >> (32 - (r))); x1 ^= x0; }
    TF_ROUND(13) TF_ROUND(15) TF_ROUND(26) TF_ROUND(6)
    x0 += k1; x1 += k2 + 1u;
    TF_ROUND(17) TF_ROUND(29) TF_ROUND(16) TF_ROUND(24)
    x0 += k2; x1 += k0 + 2u;
    TF_ROUND(13) TF_ROUND(15) TF_ROUND(26) TF_ROUND(6)
    x0 += k0; x1 += k1 + 3u;
    TF_ROUND(17) TF_ROUND(29) TF_ROUND(16) TF_ROUND(24)
    x0 += k1; x1 += k2 + 4u;
    TF_ROUND(13) TF_ROUND(15) TF_ROUND(26) TF_ROUND(6)
    x0 += k2; x1 += k0 + 5u;
#undef TF_ROUND
    o0 = x0; o1 = x1;
}

// ---------------- head ----------------
__global__ __launch_bounds__(64) void head_kernel(
    const float* __restrict__ Wmu, const float* __restrict__ bmu,
    const float* __restrict__ Wlv, const float* __restrict__ blv,
    const float* __restrict__ Wd1, const float* __restrict__ bd1,
    const float* __restrict__ Wd2, const float* __restrict__ bd2,
    float* __restrict__ out)
{
    int g = blockIdx.x;
    int t = threadIdx.x;
    __shared__ float pooled[64];
    __shared__ float zs[32];
    __shared__ float hdec[64];

    float c = fmaxf((float)g_cnt[g], 1.0f);
    pooled[t] = g_gsum[g * 64 + t] / c;
    __syncthreads();

    if (t < 32) {
        float mu = __ldg(&bmu[t]), lv = __ldg(&blv[t]);
#pragma unroll 8
        for (int k = 0; k < 64; k++) {
            float p = pooled[k];
            mu = fmaf(p, __ldg(&Wmu[k * 32 + t]), mu);
            lv = fmaf(p, __ldg(&Wlv[k * 32 + t]), lv);
        }
        unsigned idx = (unsigned)(g * 32 + t);
        unsigned b0, b1;
        threefry2x32_42(0u, idx, b0, b1);
        unsigned bits = b0 ^ b1;
        float f = __uint_as_float((bits >> 9) | 0x3f800000u) - 1.0f;
        const float LO = -0.99999994f;
        float u = fmaxf(LO, f * (1.0f - LO) + LO);
        float eps = 1.41421356237309515f * erfinvf(u);
        float z = mu + eps * expf(0.5f * lv);
        zs[t] = z;
        out[16384 + g * 32 + t] = mu;
        out[24576 + g * 32 + t] = lv;
    }
    __syncthreads();

    float hv = __ldg(&bd1[t]);
#pragma unroll 8
    for (int k = 0; k < 32; k++) hv = fmaf(zs[k], __ldg(&Wd1[k * 64 + t]), hv);
    hdec[t] = fmaxf(hv, 0.f);
    __syncthreads();

    float rv = __ldg(&bd2[t]);
#pragma unroll 8
    for (int k = 0; k < 64; k++) rv = fmaf(hdec[k], __ldg(&Wd2[k * 64 + t]), rv);
    out[g * 64 + t] = rv;
}

// ---------------- launch ----------------
extern "C" void kernel_launch(void* const* d_in, const int* in_sizes, int n_in,
                              void* d_out, int out_size)
{
    const float* x     = (const float*)d_in[0];
    const int*   ei    = (const int*)d_in[1];
    const int*   batch = (const int*)d_in[2];
    const float* W1  = (const float*)d_in[3];  const float* b1  = (const float*)d_in[4];
    const float* W2  = (const float*)d_in[5];  const float* b2  = (const float*)d_in[6];
    const float* Wmu = (const float*)d_in[7];  const float* bmu = (const float*)d_in[8];
    const float* Wlv = (const float*)d_in[9];  const float* blv = (const float*)d_in[10];
    const float* Wd1 = (const float*)d_in[11]; const float* bd1 = (const float*)d_in[12];
    const float* Wd2 = (const float*)d_in[13]; const float* bd2 = (const float*)d_in[14];
    float* out = (float*)d_out;

    void *p_h1, *p_h2;
    cudaGetSymbolAddress(&p_h1, g_h1);
    cudaGetSymbolAddress(&p_h2, g_h2);
    float* h1 = (float*)p_h1;
    float* h2 = (float*)p_h2;

    zero_kernel<<<(N_NODES + 255) / 256, 256>>>();
    hist_kernel<<<(N_EDGES + 255) / 256, 256>>>(ei, batch);
    scan_all_kernel<<<SCAN_BLOCKS, 256>>>();
    fill_kernel<<<(N_EDGES + 255) / 256, 256>>>(ei);

    int agg_grid = (N_NODES * 32 + 255) / 256;
    int gemm_grid = (N_NODES + 127) / 128;

    // layer 1:  S1 = A_hat x ;  h1 = relu(S1 W1 + b1)
    agg_kernel<<<agg_grid, 256>>>(x, h1);
    gemm_kernel<0><<<gemm_grid, 256>>>(h1, W1, b1, h2, nullptr);
    // layer 2:  S2 = A_hat h1 ;  pooled-sum of relu(S2 W2 + b2)
    agg_kernel<<<agg_grid, 256>>>(h2, h1);
    gemm_kernel<1><<<gemm_grid, 256>>>(h1, W2, b2, nullptr, batch);
    // head
    head_kernel<<<N_GRAPH, 64>>>(Wmu, bmu, Wlv, blv, Wd1, bd1, Wd2, bd2, out);
}

// round 9
// speedup vs baseline: 1.2991x; 1.0065x over previous
#include <cuda_runtime.h>
#include <cuda_bf16.h>
#include <cstdint>

#define N_NODES 100000
#define N_EDGES 1000000
#define N_GRAPH 256
#define SCAN_CH 840
#define SCAN_BLOCKS 120   // 120*840 = 100800 >= 100000

// ---------------- scratch ----------------
__device__ float g_h1[N_NODES * 64];
__device__ float g_h2[N_NODES * 64];
__device__ int   g_deg[N_NODES];
__device__ float g_dinv[N_NODES];
__device__ int   g_rowptr[N_NODES + 1];
__device__ int   g_pos[N_NODES];
__device__ int   g_csr[N_EDGES];
__device__ int   g_cnt[N_GRAPH];
__device__ float g_gsum[N_GRAPH * 64];

// ---------------- packed f32x2 helpers ----------------
__device__ __forceinline__ unsigned long long pack2(float lo, float hi)
{
    unsigned long long r;
    asm("mov.b64 %0, {%1, %2};" : "=l"(r) : "f"(lo), "f"(hi));
    return r;
}
__device__ __forceinline__ void unpack2(unsigned long long v, float& lo, float& hi)
{
    asm("mov.b64 {%0, %1}, %2;" : "=f"(lo), "=f"(hi) : "l"(v));
}
__device__ __forceinline__ void ffma2(unsigned long long& d, unsigned long long a,
                                      unsigned long long b)
{
    asm("fma.rn.f32x2 %0, %1, %2, %0;" : "+l"(d) : "l"(a), "l"(b));
}

// ---------------- zero ----------------
__global__ void zero_kernel()
{
    int i = blockIdx.x * blockDim.x + threadIdx.x;
    if (i < N_NODES) g_deg[i] = 0;
    if (i < N_GRAPH) g_cnt[i] = 0;
    if (i < N_GRAPH * 64) g_gsum[i] = 0.f;
}

// ---------------- histograms: 4 edges/thread, batched loads for MLP ----------------
__global__ void hist_kernel(const int* __restrict__ ei, const int* __restrict__ batch)
{
    int t = blockIdx.x * blockDim.x + threadIdx.x;
    int e4 = t * 4;
    if (e4 + 3 < N_EDGES) {
        int4 d = *reinterpret_cast<const int4*>(ei + N_EDGES + e4);
        if ((unsigned)d.x < (unsigned)N_NODES) atomicAdd(&g_deg[d.x], 1);
        if ((unsigned)d.y < (unsigned)N_NODES) atomicAdd(&g_deg[d.y], 1);
        if ((unsigned)d.z < (unsigned)N_NODES) atomicAdd(&g_deg[d.z], 1);
        if ((unsigned)d.w < (unsigned)N_NODES) atomicAdd(&g_deg[d.w], 1);
    } else {
        for (int e = e4; e < N_EDGES; e++) {
            int d = ei[N_EDGES + e];
            if ((unsigned)d < (unsigned)N_NODES) atomicAdd(&g_deg[d], 1);
        }
    }
    // batch histogram: 4 nodes/thread
    int n4 = t * 4;
    if (n4 + 3 < N_NODES) {
        int4 b = *reinterpret_cast<const int4*>(batch + n4);
        if ((unsigned)b.x < (unsigned)N_GRAPH) atomicAdd(&g_cnt[b.x], 1);
        if ((unsigned)b.y < (unsigned)N_GRAPH) atomicAdd(&g_cnt[b.y], 1);
        if ((unsigned)b.z < (unsigned)N_GRAPH) atomicAdd(&g_cnt[b.z], 1);
        if ((unsigned)b.w < (unsigned)N_GRAPH) atomicAdd(&g_cnt[b.w], 1);
    } else {
        for (int i = n4; i < N_NODES; i++) {
            int b = batch[i];
            if ((unsigned)b < (unsigned)N_GRAPH) atomicAdd(&g_cnt[b], 1);
        }
    }
}

// ---------------- single-kernel scan: rowptr/pos/dinv ----------------
__global__ __launch_bounds__(256) void scan_all_kernel()
{
    int b = blockIdx.x;
    int start = b * SCAN_CH;
    int end   = min(start + SCAN_CH, N_NODES);
    int lane = threadIdx.x & 31, wid = threadIdx.x >> 5;

    // --- global prefix: sum deg[0..start) ---
    int psum = 0;
#pragma unroll 4
    for (int i = threadIdx.x; i < start; i += 256) psum += g_deg[i];
#pragma unroll
    for (int o = 16; o > 0; o >>= 1) psum += __shfl_down_sync(0xffffffffu, psum, o);
    __shared__ int wred[8];
    __shared__ int s_off;
    if (lane == 0) wred[wid] = psum;
    __syncthreads();
    if (threadIdx.x == 0) {
        int t = 0;
#pragma unroll
        for (int w = 0; w < 8; w++) t += wred[w];
        s_off = t;
    }
    __syncthreads();
    int carry = s_off;

    // --- chunk scan ---
    __shared__ int wsum[8];
    __shared__ int tile_total;
    for (int base = start; base < end; base += 256) {
        int i = base + (int)threadIdx.x;
        int dv = (i < end) ? g_deg[i] : 0;
        int incl = dv;
#pragma unroll
        for (int o = 1; o < 32; o <<= 1) {
            int t = __shfl_up_sync(0xffffffffu, incl, o);
            if (lane >= o) incl += t;
        }
        if (lane == 31) wsum[wid] = incl;
        __syncthreads();
        if (threadIdx.x == 0) {
            int run = 0;
#pragma unroll
            for (int w = 0; w < 8; w++) { int t = wsum[w]; wsum[w] = run; run += t; }
            tile_total = run;
        }
        __syncthreads();
        if (i < end) {
            int r = incl - dv + wsum[wid] + carry;
            g_rowptr[i] = r;
            g_pos[i] = r;
            g_dinv[i] = rsqrtf((float)dv + 1.0f);
        }
        carry += tile_total;
        __syncthreads();
    }
    if (b == SCAN_BLOCKS - 1 && threadIdx.x == 0) g_rowptr[N_NODES] = N_EDGES;
}

// ---------------- CSR fill: 4 edges/thread, batched loads for MLP ----------------
__global__ void fill_kernel(const int* __restrict__ ei)
{
    int t = blockIdx.x * blockDim.x + threadIdx.x;
    int e4 = t * 4;
    if (e4 + 3 < N_EDGES) {
        int4 s = *reinterpret_cast<const int4*>(ei + e4);
        int4 d = *reinterpret_cast<const int4*>(ei + N_EDGES + e4);
        // 4 independent atomic chains in flight
        int p0 = ((unsigned)d.x < (unsigned)N_NODES) ? atomicAdd(&g_pos[d.x], 1) : -1;
        int p1 = ((unsigned)d.y < (unsigned)N_NODES) ? atomicAdd(&g_pos[d.y], 1) : -1;
        int p2 = ((unsigned)d.z < (unsigned)N_NODES) ? atomicAdd(&g_pos[d.z], 1) : -1;
        int p3 = ((unsigned)d.w < (unsigned)N_NODES) ? atomicAdd(&g_pos[d.w], 1) : -1;
        if ((unsigned)p0 < (unsigned)N_EDGES) g_csr[p0] = s.x;
        if ((unsigned)p1 < (unsigned)N_EDGES) g_csr[p1] = s.y;
        if ((unsigned)p2 < (unsigned)N_EDGES) g_csr[p2] = s.z;
        if ((unsigned)p3 < (unsigned)N_EDGES) g_csr[p3] = s.w;
    } else {
        for (int e = e4; e < N_EDGES; e++) {
            int s = ei[e];
            int d = ei[N_EDGES + e];
            if ((unsigned)s < (unsigned)N_NODES && (unsigned)d < (unsigned)N_NODES) {
                int p = atomicAdd(&g_pos[d], 1);
                if ((unsigned)p < (unsigned)N_EDGES) g_csr[p] = s;
            }
        }
    }
}

// ---------------- pure aggregation: S = A_hat @ X  (warp per node) ----------------
__global__ __launch_bounds__(256) void agg_kernel(const float* __restrict__ hraw,
                                                  float* __restrict__ hout)
{
    int gw = (blockIdx.x * blockDim.x + threadIdx.x) >> 5;
    if (gw >= N_NODES) return;
    int lane = threadIdx.x & 31;

    const float2* h = reinterpret_cast<const float2*>(hraw);
    float di = g_dinv[gw];
    float2 self = __ldg(&h[(size_t)gw * 32 + lane]);
    float d2 = di * di;
    float2 acc = make_float2(d2 * self.x, d2 * self.y);

    int e  = g_rowptr[gw];
    int e1 = g_rowptr[gw + 1];
    for (; e + 3 < e1; e += 4) {
        int s0 = g_csr[e], s1 = g_csr[e + 1], s2 = g_csr[e + 2], s3 = g_csr[e + 3];
        float w0 = __ldg(&g_dinv[s0]);
        float w1 = __ldg(&g_dinv[s1]);
        float w2 = __ldg(&g_dinv[s2]);
        float w3 = __ldg(&g_dinv[s3]);
        float2 h0 = __ldg(&h[(size_t)s0 * 32 + lane]);
        float2 h1 = __ldg(&h[(size_t)s1 * 32 + lane]);
        float2 h2 = __ldg(&h[(size_t)s2 * 32 + lane]);
        float2 h3 = __ldg(&h[(size_t)s3 * 32 + lane]);
        w0 *= di; w1 *= di; w2 *= di; w3 *= di;
        acc.x = fmaf(w0, h0.x, acc.x); acc.y = fmaf(w0, h0.y, acc.y);
        acc.x = fmaf(w1, h1.x, acc.x); acc.y = fmaf(w1, h1.y, acc.y);
        acc.x = fmaf(w2, h2.x, acc.x); acc.y = fmaf(w2, h2.y, acc.y);
        acc.x = fmaf(w3, h3.x, acc.x); acc.y = fmaf(w3, h3.y, acc.y);
    }
    for (; e < e1; e++) {
        int s0 = g_csr[e];
        float w0 = di * __ldg(&g_dinv[s0]);
        float2 h0 = __ldg(&h[(size_t)s0 * 32 + lane]);
        acc.x = fmaf(w0, h0.x, acc.x); acc.y = fmaf(w0, h0.y, acc.y);
    }
    reinterpret_cast<float2*>(hout)[(size_t)gw * 32 + lane] = acc;
}

// ---------------- blocked GEMM: Y = relu(X @ W + b), optional fused pool ----------------
template <int POOL>
__global__ __launch_bounds__(256) void gemm_kernel(const float* __restrict__ X,
                                                   const float* __restrict__ W,
                                                   const float* __restrict__ bias,
                                                   float* __restrict__ Y,
                                                   const int* __restrict__ batch)
{
    __shared__ float Xs[128][68];     // padded
    __shared__ float Ws[64][64];
    int tid = threadIdx.x;
    int mbase = blockIdx.x * 128;

#pragma unroll
    for (int t = 0; t < 8; t++) {
        int i = tid + t * 256;
        int r = i >> 4, c4 = (i & 15) * 4;
        int grow = mbase + r;
        float4 v = make_float4(0.f, 0.f, 0.f, 0.f);
        if (grow < N_NODES) v = __ldg((const float4*)(X + (size_t)grow * 64 + c4));
        *(float4*)&Xs[r][c4] = v;
    }
#pragma unroll
    for (int t = 0; t < 4; t++) {
        int i = tid + t * 256;
        int k = i >> 4, c4 = (i & 15) * 4;
        *(float4*)&Ws[k][c4] = __ldg((const float4*)(W + k * 64 + c4));
    }
    __syncthreads();

    int tg_m = tid >> 4;
    int tg_n = tid & 15;
    int mloc = tg_m * 8;
    int n0 = tg_n * 4;

    unsigned long long acc[8][4];
#pragma unroll
    for (int r = 0; r < 8; r++)
#pragma unroll
        for (int c = 0; c < 4; c++) acc[r][c] = 0ull;

#pragma unroll 4
    for (int k = 0; k < 64; k += 2) {
        float4 wa = *(const float4*)&Ws[k][n0];
        float4 wb = *(const float4*)&Ws[k + 1][n0];
        unsigned long long wp0 = pack2(wa.x, wb.x);
        unsigned long long wp1 = pack2(wa.y, wb.y);
        unsigned long long wp2 = pack2(wa.z, wb.z);
        unsigned long long wp3 = pack2(wa.w, wb.w);
#pragma unroll
        for (int r = 0; r < 8; r++) {
            unsigned long long xp = *(const unsigned long long*)&Xs[mloc + r][k];
            ffma2(acc[r][0], xp, wp0);
            ffma2(acc[r][1], xp, wp1);
            ffma2(acc[r][2], xp, wp2);
            ffma2(acc[r][3], xp, wp3);
        }
    }

    float4 bv = __ldg((const float4*)(bias + n0));

    if (POOL) {
        float p0 = 0.f, p1 = 0.f, p2 = 0.f, p3 = 0.f;
        int curg = -1;
#pragma unroll
        for (int r = 0; r < 8; r++) {
            int grow = mbase + mloc + r;
            if (grow >= N_NODES) break;
            int g = batch[grow];
            if (g != curg) {
                if (curg >= 0 && (unsigned)curg < (unsigned)N_GRAPH) {
                    atomicAdd(&g_gsum[curg * 64 + n0],     p0);
                    atomicAdd(&g_gsum[curg * 64 + n0 + 1], p1);
                    atomicAdd(&g_gsum[curg * 64 + n0 + 2], p2);
                    atomicAdd(&g_gsum[curg * 64 + n0 + 3], p3);
                }
                curg = g; p0 = p1 = p2 = p3 = 0.f;
            }
            float lo, hi;
            unpack2(acc[r][0], lo, hi); p0 += fmaxf(lo + hi + bv.x, 0.f);
            unpack2(acc[r][1], lo, hi); p1 += fmaxf(lo + hi + bv.y, 0.f);
            unpack2(acc[r][2], lo, hi); p2 += fmaxf(lo + hi + bv.z, 0.f);
            unpack2(acc[r][3], lo, hi); p3 += fmaxf(lo + hi + bv.w, 0.f);
        }
        if (curg >= 0 && (unsigned)curg < (unsigned)N_GRAPH) {
            atomicAdd(&g_gsum[curg * 64 + n0],     p0);
            atomicAdd(&g_gsum[curg * 64 + n0 + 1], p1);
            atomicAdd(&g_gsum[curg * 64 + n0 + 2], p2);
            atomicAdd(&g_gsum[curg * 64 + n0 + 3], p3);
        }
    } else {
#pragma unroll
        for (int r = 0; r < 8; r++) {
            int grow = mbase + mloc + r;
            if (grow >= N_NODES) break;
            float lo, hi;
            float4 o;
            unpack2(acc[r][0], lo, hi); o.x = fmaxf(lo + hi + bv.x, 0.f);
            unpack2(acc[r][1], lo, hi); o.y = fmaxf(lo + hi + bv.y, 0.f);
            unpack2(acc[r][2], lo, hi); o.z = fmaxf(lo + hi + bv.z, 0.f);
            unpack2(acc[r][3], lo, hi); o.w = fmaxf(lo + hi + bv.w, 0.f);
            *(float4*)(Y + (size_t)grow * 64 + n0) = o;
        }
    }
}

// ---------------- threefry-2x32, key = (0, 42) ----------------
__device__ __forceinline__ void threefry2x32_42(unsigned c0, unsigned c1,
                                                unsigned& o0, unsigned& o1)
{
    const unsigned k0 = 0u, k1 = 42u, k2 = 0u ^ 42u ^ 0x1BD11BDAu;
    unsigned x0 = c0 + k0, x1 = c1 + k1;
#define TF_ROUND(r) { x0 += x1; x1 = (x1 << (r)) | (x1 >> (32 - (r))); x1 ^= x0; }
    TF_ROUND(13) TF_ROUND(15) TF_ROUND(26) TF_ROUND(6)
    x0 += k1; x1 += k2 + 1u;
    TF_ROUND(17) TF_ROUND(29) TF_ROUND(16) TF_ROUND(24)
    x0 += k2; x1 += k0 + 2u;
    TF_ROUND(13) TF_ROUND(15) TF_ROUND(26) TF_ROUND(6)
    x0 += k0; x1 += k1 + 3u;
    TF_ROUND(17) TF_ROUND(29) TF_ROUND(16) TF_ROUND(24)
    x0 += k1; x1 += k2 + 4u;
    TF_ROUND(13) TF_ROUND(15) TF_ROUND(26) TF_ROUND(6)
    x0 += k2; x1 += k0 + 5u;
#undef TF_ROUND
    o0 = x0; o1 = x1;
}

// ---------------- head ----------------
__global__ __launch_bounds__(64) void head_kernel(
    const float* __restrict__ Wmu, const float* __restrict__ bmu,
    const float* __restrict__ Wlv, const float* __restrict__ blv,
    const float* __restrict__ Wd1, const float* __restrict__ bd1,
    const float* __restrict__ Wd2, const float* __restrict__ bd2,
    float* __restrict__ out)
{
    int g = blockIdx.x;
    int t = threadIdx.x;
    __shared__ float pooled[64];
    __shared__ float zs[32];
    __shared__ float hdec[64];

    float c = fmaxf((float)g_cnt[g], 1.0f);
    pooled[t] = g_gsum[g * 64 + t] / c;
    __syncthreads();

    if (t < 32) {
        float mu = __ldg(&bmu[t]), lv = __ldg(&blv[t]);
#pragma unroll 8
        for (int k = 0; k < 64; k++) {
            float p = pooled[k];
            mu = fmaf(p, __ldg(&Wmu[k * 32 + t]), mu);
            lv = fmaf(p, __ldg(&Wlv[k * 32 + t]), lv);
        }
        unsigned idx = (unsigned)(g * 32 + t);
        unsigned b0, b1;
        threefry2x32_42(0u, idx, b0, b1);
        unsigned bits = b0 ^ b1;
        float f = __uint_as_float((bits >> 9) | 0x3f800000u) - 1.0f;
        const float LO = -0.99999994f;
        float u = fmaxf(LO, f * (1.0f - LO) + LO);
        float eps = 1.41421356237309515f * erfinvf(u);
        float z = mu + eps * expf(0.5f * lv);
        zs[t] = z;
        out[16384 + g * 32 + t] = mu;
        out[24576 + g * 32 + t] = lv;
    }
    __syncthreads();

    float hv = __ldg(&bd1[t]);
#pragma unroll 8
    for (int k = 0; k < 32; k++) hv = fmaf(zs[k], __ldg(&Wd1[k * 64 + t]), hv);
    hdec[t] = fmaxf(hv, 0.f);
    __syncthreads();

    float rv = __ldg(&bd2[t]);
#pragma unroll 8
    for (int k = 0; k < 64; k++) rv = fmaf(hdec[k], __ldg(&Wd2[k * 64 + t]), rv);
    out[g * 64 + t] = rv;
}

// ---------------- launch ----------------
extern "C" void kernel_launch(void* const* d_in, const int* in_sizes, int n_in,
                              void* d_out, int out_size)
{
    const float* x     = (const float*)d_in[0];
    const int*   ei    = (const int*)d_in[1];
    const int*   batch = (const int*)d_in[2];
    const float* W1  = (const float*)d_in[3];  const float* b1  = (const float*)d_in[4];
    const float* W2  = (const float*)d_in[5];  const float* b2  = (const float*)d_in[6];
    const float* Wmu = (const float*)d_in[7];  const float* bmu = (const float*)d_in[8];
    const float* Wlv = (const float*)d_in[9];  const float* blv = (const float*)d_in[10];
    const float* Wd1 = (const float*)d_in[11]; const float* bd1 = (const float*)d_in[12];
    const float* Wd2 = (const float*)d_in[13]; const float* bd2 = (const float*)d_in[14];
    float* out = (float*)d_out;

    void *p_h1, *p_h2;
    cudaGetSymbolAddress(&p_h1, g_h1);
    cudaGetSymbolAddress(&p_h2, g_h2);
    float* h1 = (float*)p_h1;
    float* h2 = (float*)p_h2;

    zero_kernel<<<(N_NODES + 255) / 256, 256>>>();
    hist_kernel<<<(N_EDGES / 4 + 255) / 256, 256>>>(ei, batch);
    scan_all_kernel<<<SCAN_BLOCKS, 256>>>();
    fill_kernel<<<(N_EDGES / 4 + 255) / 256, 256>>>(ei);

    int agg_grid = (N_NODES * 32 + 255) / 256;
    int gemm_grid = (N_NODES + 127) / 128;

    // layer 1:  S1 = A_hat x ;  h1 = relu(S1 W1 + b1)
    agg_kernel<<<agg_grid, 256>>>(x, h1);
    gemm_kernel<0><<<gemm_grid, 256>>>(h1, W1, b1, h2, nullptr);
    // layer 2:  S2 = A_hat h1 ;  pooled-sum of relu(S2 W2 + b2)
    agg_kernel<<<agg_grid, 256>>>(h2, h1);
    gemm_kernel<1><<<gemm_grid, 256>>>(h1, W2, b2, nullptr, batch);
    // head
    head_kernel<<<N_GRAPH, 64>>>(Wmu, bmu, Wlv, blv, Wd1, bd1, Wd2, bd2, out);
}

// round 10
// speedup vs baseline: 1.3107x; 1.0089x over previous
#include <cuda_runtime.h>
#include <cuda_bf16.h>
#include <cstdint>

#define N_NODES 100000
#define N_EDGES 1000000
#define N_GRAPH 256
#define SCAN_CH 840
#define SCAN_BLOCKS 120   // 120*840 = 100800 >= 100000

// ---------------- scratch ----------------
__device__ float g_h1[N_NODES * 64];
__device__ float g_h2[N_NODES * 64];
__device__ int   g_deg[N_NODES];
__device__ float g_dinv[N_NODES];
__device__ int   g_rowptr[N_NODES + 1];
__device__ int   g_rank[N_EDGES];          // rank of edge within its dst row
__device__ int   g_csr[N_EDGES];
__device__ int   g_cnt[N_GRAPH];
__device__ float g_gsum[N_GRAPH * 64];

// ---------------- packed f32x2 helpers ----------------
__device__ __forceinline__ unsigned long long pack2(float lo, float hi)
{
    unsigned long long r;
    asm("mov.b64 %0, {%1, %2};" : "=l"(r) : "f"(lo), "f"(hi));
    return r;
}
__device__ __forceinline__ void unpack2(unsigned long long v, float& lo, float& hi)
{
    asm("mov.b64 {%0, %1}, %2;" : "=f"(lo), "=f"(hi) : "l"(v));
}
__device__ __forceinline__ void ffma2(unsigned long long& d, unsigned long long a,
                                      unsigned long long b)
{
    asm("fma.rn.f32x2 %0, %1, %2, %0;" : "+l"(d) : "l"(a), "l"(b));
}

// ---------------- zero ----------------
__global__ void zero_kernel()
{
    int i = blockIdx.x * blockDim.x + threadIdx.x;
    if (i < N_NODES) g_deg[i] = 0;
    if (i < N_GRAPH) g_cnt[i] = 0;
    if (i < N_GRAPH * 64) g_gsum[i] = 0.f;
}

// ---------------- histograms: degree atomic doubles as rank assignment ----------------
__global__ void hist_kernel(const int* __restrict__ ei, const int* __restrict__ batch)
{
    int t = blockIdx.x * blockDim.x + threadIdx.x;
    int e4 = t * 4;
    if (e4 + 3 < N_EDGES) {
        int4 d = *reinterpret_cast<const int4*>(ei + N_EDGES + e4);
        int r0 = ((unsigned)d.x < (unsigned)N_NODES) ? atomicAdd(&g_deg[d.x], 1) : 0;
        int r1 = ((unsigned)d.y < (unsigned)N_NODES) ? atomicAdd(&g_deg[d.y], 1) : 0;
        int r2 = ((unsigned)d.z < (unsigned)N_NODES) ? atomicAdd(&g_deg[d.z], 1) : 0;
        int r3 = ((unsigned)d.w < (unsigned)N_NODES) ? atomicAdd(&g_deg[d.w], 1) : 0;
        *reinterpret_cast<int4*>(g_rank + e4) = make_int4(r0, r1, r2, r3);
    } else {
        for (int e = e4; e < N_EDGES; e++) {
            int d = ei[N_EDGES + e];
            g_rank[e] = ((unsigned)d < (unsigned)N_NODES) ? atomicAdd(&g_deg[d], 1) : 0;
        }
    }
    // batch histogram: 4 nodes/thread
    int n4 = t * 4;
    if (n4 + 3 < N_NODES) {
        int4 b = *reinterpret_cast<const int4*>(batch + n4);
        if ((unsigned)b.x < (unsigned)N_GRAPH) atomicAdd(&g_cnt[b.x], 1);
        if ((unsigned)b.y < (unsigned)N_GRAPH) atomicAdd(&g_cnt[b.y], 1);
        if ((unsigned)b.z < (unsigned)N_GRAPH) atomicAdd(&g_cnt[b.z], 1);
        if ((unsigned)b.w < (unsigned)N_GRAPH) atomicAdd(&g_cnt[b.w], 1);
    } else {
        for (int i = n4; i < N_NODES; i++) {
            int b = batch[i];
            if ((unsigned)b < (unsigned)N_GRAPH) atomicAdd(&g_cnt[b], 1);
        }
    }
}

// ---------------- single-kernel scan: rowptr/dinv ----------------
__global__ __launch_bounds__(256) void scan_all_kernel()
{
    int b = blockIdx.x;
    int start = b * SCAN_CH;
    int end   = min(start + SCAN_CH, N_NODES);
    int lane = threadIdx.x & 31, wid = threadIdx.x >> 5;

    // --- global prefix: sum deg[0..start) ---
    int psum = 0;
#pragma unroll 4
    for (int i = threadIdx.x; i < start; i += 256) psum += g_deg[i];
#pragma unroll
    for (int o = 16; o > 0; o >>= 1) psum += __shfl_down_sync(0xffffffffu, psum, o);
    __shared__ int wred[8];
    __shared__ int s_off;
    if (lane == 0) wred[wid] = psum;
    __syncthreads();
    if (threadIdx.x == 0) {
        int t = 0;
#pragma unroll
        for (int w = 0; w < 8; w++) t += wred[w];
        s_off = t;
    }
    __syncthreads();
    int carry = s_off;

    // --- chunk scan ---
    __shared__ int wsum[8];
    __shared__ int tile_total;
    for (int base = start; base < end; base += 256) {
        int i = base + (int)threadIdx.x;
        int dv = (i < end) ? g_deg[i] : 0;
        int incl = dv;
#pragma unroll
        for (int o = 1; o < 32; o <<= 1) {
            int t = __shfl_up_sync(0xffffffffu, incl, o);
            if (lane >= o) incl += t;
        }
        if (lane == 31) wsum[wid] = incl;
        __syncthreads();
        if (threadIdx.x == 0) {
            int run = 0;
#pragma unroll
            for (int w = 0; w < 8; w++) { int t = wsum[w]; wsum[w] = run; run += t; }
            tile_total = run;
        }
        __syncthreads();
        if (i < end) {
            int r = incl - dv + wsum[wid] + carry;
            g_rowptr[i] = r;
            g_dinv[i] = rsqrtf((float)dv + 1.0f);
        }
        carry += tile_total;
        __syncthreads();
    }
    if (b == SCAN_BLOCKS - 1 && threadIdx.x == 0) g_rowptr[N_NODES] = N_EDGES;
}

// ---------------- CSR fill: atomic-free (slot = rowptr[dst] + rank[e]) ----------------
__global__ void fill_kernel(const int* __restrict__ ei)
{
    int t = blockIdx.x * blockDim.x + threadIdx.x;
    int e4 = t * 4;
    if (e4 + 3 < N_EDGES) {
        int4 s = *reinterpret_cast<const int4*>(ei + e4);
        int4 d = *reinterpret_cast<const int4*>(ei + N_EDGES + e4);
        int4 r = *reinterpret_cast<const int4*>(g_rank + e4);
        int p0 = ((unsigned)d.x < (unsigned)N_NODES) ? __ldg(&g_rowptr[d.x]) + r.x : -1;
        int p1 = ((unsigned)d.y < (unsigned)N_NODES) ? __ldg(&g_rowptr[d.y]) + r.y : -1;
        int p2 = ((unsigned)d.z < (unsigned)N_NODES) ? __ldg(&g_rowptr[d.z]) + r.z : -1;
        int p3 = ((unsigned)d.w < (unsigned)N_NODES) ? __ldg(&g_rowptr[d.w]) + r.w : -1;
        if ((unsigned)p0 < (unsigned)N_EDGES) g_csr[p0] = s.x;
        if ((unsigned)p1 < (unsigned)N_EDGES) g_csr[p1] = s.y;
        if ((unsigned)p2 < (unsigned)N_EDGES) g_csr[p2] = s.z;
        if ((unsigned)p3 < (unsigned)N_EDGES) g_csr[p3] = s.w;
    } else {
        for (int e = e4; e < N_EDGES; e++) {
            int s = ei[e];
            int d = ei[N_EDGES + e];
            if ((unsigned)s < (unsigned)N_NODES && (unsigned)d < (unsigned)N_NODES) {
                int p = __ldg(&g_rowptr[d]) + g_rank[e];
                if ((unsigned)p < (unsigned)N_EDGES) g_csr[p] = s;
            }
        }
    }
}

// ---------------- pure aggregation: S = A_hat @ X  (warp per node) ----------------
__global__ __launch_bounds__(256) void agg_kernel(const float* __restrict__ hraw,
                                                  float* __restrict__ hout)
{
    int gw = (blockIdx.x * blockDim.x + threadIdx.x) >> 5;
    if (gw >= N_NODES) return;
    int lane = threadIdx.x & 31;

    const float2* h = reinterpret_cast<const float2*>(hraw);
    float di = g_dinv[gw];
    float2 self = __ldg(&h[(size_t)gw * 32 + lane]);
    float d2 = di * di;
    float2 acc = make_float2(d2 * self.x, d2 * self.y);

    int e  = g_rowptr[gw];
    int e1 = g_rowptr[gw + 1];
    for (; e + 3 < e1; e += 4) {
        int s0 = g_csr[e], s1 = g_csr[e + 1], s2 = g_csr[e + 2], s3 = g_csr[e + 3];
        float w0 = __ldg(&g_dinv[s0]);
        float w1 = __ldg(&g_dinv[s1]);
        float w2 = __ldg(&g_dinv[s2]);
        float w3 = __ldg(&g_dinv[s3]);
        float2 h0 = __ldg(&h[(size_t)s0 * 32 + lane]);
        float2 h1 = __ldg(&h[(size_t)s1 * 32 + lane]);
        float2 h2 = __ldg(&h[(size_t)s2 * 32 + lane]);
        float2 h3 = __ldg(&h[(size_t)s3 * 32 + lane]);
        w0 *= di; w1 *= di; w2 *= di; w3 *= di;
        acc.x = fmaf(w0, h0.x, acc.x); acc.y = fmaf(w0, h0.y, acc.y);
        acc.x = fmaf(w1, h1.x, acc.x); acc.y = fmaf(w1, h1.y, acc.y);
        acc.x = fmaf(w2, h2.x, acc.x); acc.y = fmaf(w2, h2.y, acc.y);
        acc.x = fmaf(w3, h3.x, acc.x); acc.y = fmaf(w3, h3.y, acc.y);
    }
    for (; e < e1; e++) {
        int s0 = g_csr[e];
        float w0 = di * __ldg(&g_dinv[s0]);
        float2 h0 = __ldg(&h[(size_t)s0 * 32 + lane]);
        acc.x = fmaf(w0, h0.x, acc.x); acc.y = fmaf(w0, h0.y, acc.y);
    }
    reinterpret_cast<float2*>(hout)[(size_t)gw * 32 + lane] = acc;
}

// ---------------- blocked GEMM: Y = relu(X @ W + b), optional fused pool ----------------
template <int POOL>
__global__ __launch_bounds__(256) void gemm_kernel(const float* __restrict__ X,
                                                   const float* __restrict__ W,
                                                   const float* __restrict__ bias,
                                                   float* __restrict__ Y,
                                                   const int* __restrict__ batch)
{
    __shared__ float Xs[128][68];     // padded
    __shared__ float Ws[64][64];
    int tid = threadIdx.x;
    int mbase = blockIdx.x * 128;

#pragma unroll
    for (int t = 0; t < 8; t++) {
        int i = tid + t * 256;
        int r = i >> 4, c4 = (i & 15) * 4;
        int grow = mbase + r;
        float4 v = make_float4(0.f, 0.f, 0.f, 0.f);
        if (grow < N_NODES) v = __ldg((const float4*)(X + (size_t)grow * 64 + c4));
        *(float4*)&Xs[r][c4] = v;
    }
#pragma unroll
    for (int t = 0; t < 4; t++) {
        int i = tid + t * 256;
        int k = i >> 4, c4 = (i & 15) * 4;
        *(float4*)&Ws[k][c4] = __ldg((const float4*)(W + k * 64 + c4));
    }
    __syncthreads();

    int tg_m = tid >> 4;
    int tg_n = tid & 15;
    int mloc = tg_m * 8;
    int n0 = tg_n * 4;

    unsigned long long acc[8][4];
#pragma unroll
    for (int r = 0; r < 8; r++)
#pragma unroll
        for (int c = 0; c < 4; c++) acc[r][c] = 0ull;

#pragma unroll 4
    for (int k = 0; k < 64; k += 2) {
        float4 wa = *(const float4*)&Ws[k][n0];
        float4 wb = *(const float4*)&Ws[k + 1][n0];
        unsigned long long wp0 = pack2(wa.x, wb.x);
        unsigned long long wp1 = pack2(wa.y, wb.y);
        unsigned long long wp2 = pack2(wa.z, wb.z);
        unsigned long long wp3 = pack2(wa.w, wb.w);
#pragma unroll
        for (int r = 0; r < 8; r++) {
            unsigned long long xp = *(const unsigned long long*)&Xs[mloc + r][k];
            ffma2(acc[r][0], xp, wp0);
            ffma2(acc[r][1], xp, wp1);
            ffma2(acc[r][2], xp, wp2);
            ffma2(acc[r][3], xp, wp3);
        }
    }

    float4 bv = __ldg((const float4*)(bias + n0));

    if (POOL) {
        float p0 = 0.f, p1 = 0.f, p2 = 0.f, p3 = 0.f;
        int curg = -1;
#pragma unroll
        for (int r = 0; r < 8; r++) {
            int grow = mbase + mloc + r;
            if (grow >= N_NODES) break;
            int g = batch[grow];
            if (g != curg) {
                if (curg >= 0 && (unsigned)curg < (unsigned)N_GRAPH) {
                    atomicAdd(&g_gsum[curg * 64 + n0],     p0);
                    atomicAdd(&g_gsum[curg * 64 + n0 + 1], p1);
                    atomicAdd(&g_gsum[curg * 64 + n0 + 2], p2);
                    atomicAdd(&g_gsum[curg * 64 + n0 + 3], p3);
                }
                curg = g; p0 = p1 = p2 = p3 = 0.f;
            }
            float lo, hi;
            unpack2(acc[r][0], lo, hi); p0 += fmaxf(lo + hi + bv.x, 0.f);
            unpack2(acc[r][1], lo, hi); p1 += fmaxf(lo + hi + bv.y, 0.f);
            unpack2(acc[r][2], lo, hi); p2 += fmaxf(lo + hi + bv.z, 0.f);
            unpack2(acc[r][3], lo, hi); p3 += fmaxf(lo + hi + bv.w, 0.f);
        }
        if (curg >= 0 && (unsigned)curg < (unsigned)N_GRAPH) {
            atomicAdd(&g_gsum[curg * 64 + n0],     p0);
            atomicAdd(&g_gsum[curg * 64 + n0 + 1], p1);
            atomicAdd(&g_gsum[curg * 64 + n0 + 2], p2);
            atomicAdd(&g_gsum[curg * 64 + n0 + 3], p3);
        }
    } else {
#pragma unroll
        for (int r = 0; r < 8; r++) {
            int grow = mbase + mloc + r;
            if (grow >= N_NODES) break;
            float lo, hi;
            float4 o;
            unpack2(acc[r][0], lo, hi); o.x = fmaxf(lo + hi + bv.x, 0.f);
            unpack2(acc[r][1], lo, hi); o.y = fmaxf(lo + hi + bv.y, 0.f);
            unpack2(acc[r][2], lo, hi); o.z = fmaxf(lo + hi + bv.z, 0.f);
            unpack2(acc[r][3], lo, hi); o.w = fmaxf(lo + hi + bv.w, 0.f);
            *(float4*)(Y + (size_t)grow * 64 + n0) = o;
        }
    }
}

// ---------------- threefry-2x32, key = (0, 42) ----------------
__device__ __forceinline__ void threefry2x32_42(unsigned c0, unsigned c1,
                                                unsigned& o0, unsigned& o1)
{
    const unsigned k0 = 0u, k1 = 42u, k2 = 0u ^ 42u ^ 0x1BD11BDAu;
    unsigned x0 = c0 + k0, x1 = c1 + k1;
#define TF_ROUND(r) { x0 += x1; x1 = (x1 << (r)) | (x1 >> (32 - (r))); x1 ^= x0; }
    TF_ROUND(13) TF_ROUND(15) TF_ROUND(26) TF_ROUND(6)
    x0 += k1; x1 += k2 + 1u;
    TF_ROUND(17) TF_ROUND(29) TF_ROUND(16) TF_ROUND(24)
    x0 += k2; x1 += k0 + 2u;
    TF_ROUND(13) TF_ROUND(15) TF_ROUND(26) TF_ROUND(6)
    x0 += k0; x1 += k1 + 3u;
    TF_ROUND(17) TF_ROUND(29) TF_ROUND(16) TF_ROUND(24)
    x0 += k1; x1 += k2 + 4u;
    TF_ROUND(13) TF_ROUND(15) TF_ROUND(26) TF_ROUND(6)
    x0 += k2; x1 += k0 + 5u;
#undef TF_ROUND
    o0 = x0; o1 = x1;
}

// ---------------- head ----------------
__global__ __launch_bounds__(64) void head_kernel(
    const float* __restrict__ Wmu, const float* __restrict__ bmu,
    const float* __restrict__ Wlv, const float* __restrict__ blv,
    const float* __restrict__ Wd1, const float* __restrict__ bd1,
    const float* __restrict__ Wd2, const float* __restrict__ bd2,
    float* __restrict__ out)
{
    int g = blockIdx.x;
    int t = threadIdx.x;
    __shared__ float pooled[64];
    __shared__ float zs[32];
    __shared__ float hdec[64];

    float c = fmaxf((float)g_cnt[g], 1.0f);
    pooled[t] = g_gsum[g * 64 + t] / c;
    __syncthreads();

    if (t < 32) {
        float mu = __ldg(&bmu[t]), lv = __ldg(&blv[t]);
#pragma unroll 8
        for (int k = 0; k < 64; k++) {
            float p = pooled[k];
            mu = fmaf(p, __ldg(&Wmu[k * 32 + t]), mu);
            lv = fmaf(p, __ldg(&Wlv[k * 32 + t]), lv);
        }
        unsigned idx = (unsigned)(g * 32 + t);
        unsigned b0, b1;
        threefry2x32_42(0u, idx, b0, b1);
        unsigned bits = b0 ^ b1;
        float f = __uint_as_float((bits >> 9) | 0x3f800000u) - 1.0f;
        const float LO = -0.99999994f;
        float u = fmaxf(LO, f * (1.0f - LO) + LO);
        float eps = 1.41421356237309515f * erfinvf(u);
        float z = mu + eps * expf(0.5f * lv);
        zs[t] = z;
        out[16384 + g * 32 + t] = mu;
        out[24576 + g * 32 + t] = lv;
    }
    __syncthreads();

    float hv = __ldg(&bd1[t]);
#pragma unroll 8
    for (int k = 0; k < 32; k++) hv = fmaf(zs[k], __ldg(&Wd1[k * 64 + t]), hv);
    hdec[t] = fmaxf(hv, 0.f);
    __syncthreads();

    float rv = __ldg(&bd2[t]);
#pragma unroll 8
    for (int k = 0; k < 64; k++) rv = fmaf(hdec[k], __ldg(&Wd2[k * 64 + t]), rv);
    out[g * 64 + t] = rv;
}

// ---------------- launch ----------------
extern "C" void kernel_launch(void* const* d_in, const int* in_sizes, int n_in,
                              void* d_out, int out_size)
{
    const float* x     = (const float*)d_in[0];
    const int*   ei    = (const int*)d_in[1];
    const int*   batch = (const int*)d_in[2];
    const float* W1  = (const float*)d_in[3];  const float* b1  = (const float*)d_in[4];
    const float* W2  = (const float*)d_in[5];  const float* b2  = (const float*)d_in[6];
    const float* Wmu = (const float*)d_in[7];  const float* bmu = (const float*)d_in[8];
    const float* Wlv = (const float*)d_in[9];  const float* blv = (const float*)d_in[10];
    const float* Wd1 = (const float*)d_in[11]; const float* bd1 = (const float*)d_in[12];
    const float* Wd2 = (const float*)d_in[13]; const float* bd2 = (const float*)d_in[14];
    float* out = (float*)d_out;

    void *p_h1, *p_h2;
    cudaGetSymbolAddress(&p_h1, g_h1);
    cudaGetSymbolAddress(&p_h2, g_h2);
    float* h1 = (float*)p_h1;
    float* h2 = (float*)p_h2;

    zero_kernel<<<(N_NODES + 255) / 256, 256>>>();
    hist_kernel<<<(N_EDGES / 4 + 255) / 256, 256>>>(ei, batch);
    scan_all_kernel<<<SCAN_BLOCKS, 256>>>();
    fill_kernel<<<(N_EDGES / 4 + 255) / 256, 256>>>(ei);

    int agg_grid = (N_NODES * 32 + 255) / 256;
    int gemm_grid = (N_NODES + 127) / 128;

    // layer 1:  S1 = A_hat x ;  h1 = relu(S1 W1 + b1)
    agg_kernel<<<agg_grid, 256>>>(x, h1);
    gemm_kernel<0><<<gemm_grid, 256>>>(h1, W1, b1, h2, nullptr);
    // layer 2:  S2 = A_hat h1 ;  pooled-sum of relu(S2 W2 + b2)
    agg_kernel<<<agg_grid, 256>>>(h2, h1);
    gemm_kernel<1><<<gemm_grid, 256>>>(h1, W2, b2, nullptr, batch);
    // head
    head_kernel<<<N_GRAPH, 64>>>(Wmu, bmu, Wlv, blv, Wd1, bd1, Wd2, bd2, out);
}